// round 1
// baseline (speedup 1.0000x reference)
#include <cuda_runtime.h>
#include <math.h>

#define BSZ   4096
#define NROWS 8192
#define DIM   128
#define TS    128
#define LDSTR (TS + 4)          // 132: float4-aligned, breaks bank conflicts
#define INV_T (1.0f / 0.07f)

// Scratch (allocation-free rule: __device__ globals)
__device__ float  g_U[NROWS * DIM];   // normalized features, view-major [N, D]
__device__ float  g_S[NROWS];         // neg_row_sum per row
__device__ int    g_lab[BSZ];         // int32 labels
__device__ double g_loss;

// ---------------------------------------------------------------------------
// Kernel A: normalize rows of cf = concat(view0, view1); zero accumulators;
//           copy labels (with int64/int32 width auto-detect).
// ---------------------------------------------------------------------------
__global__ void prep_kernel(const float* __restrict__ feat,
                            const void* __restrict__ labels_raw) {
    int t    = blockIdx.x * blockDim.x + threadIdx.x;
    int warp = t >> 5;
    int lane = t & 31;

    if (t < NROWS) g_S[t] = 0.0f;
    if (t == 0)    g_loss = 0.0;
    if (t < BSZ) {
        // detect int64 vs int32: int64 labels (0..99) have all odd 32-bit words == 0
        const int* li = (const int*)labels_raw;
        bool is64 = true;
        #pragma unroll
        for (int q = 1; q < 64; q += 2) is64 &= (li[q] == 0);
        g_lab[t] = is64 ? (int)((const long long*)labels_raw)[t] : li[t];
    }

    if (warp >= NROWS) return;
    int i = warp;
    int v = i >> 12;          // view
    int b = i & (BSZ - 1);    // batch index
    const float4* src = (const float4*)&feat[(size_t)(b * 2 + v) * DIM];
    float4 f = src[lane];
    float ss = f.x * f.x + f.y * f.y + f.z * f.z + f.w * f.w;
    #pragma unroll
    for (int o = 16; o > 0; o >>= 1) ss += __shfl_xor_sync(0xffffffffu, ss, o);
    float rn = rsqrtf(ss);
    float4 u = make_float4(f.x * rn, f.y * rn, f.z * rn, f.w * rn);
    ((float4*)&g_U[(size_t)i * DIM])[lane] = u;
}

// ---------------------------------------------------------------------------
// Kernel B: upper-triangle 128x128 tiles of logits = (U U^T)/T.
//           Fused exp + negative mask; row sums AND column sums (symmetry)
//           atomically accumulated into g_S. Nothing else stored.
// ---------------------------------------------------------------------------
extern __shared__ float smem[];

__global__ __launch_bounds__(256, 1) void gemm_negsum_kernel() {
    int bi = blockIdx.y, bj = blockIdx.x;
    if (bj < bi) return;                       // upper triangle only
    bool diag = (bi == bj);
    int I0 = bi * TS, J0 = bj * TS;

    float* A_s = smem;                          // [128][132]
    float* B_s = smem + TS * LDSTR;
    __shared__ float s_row[TS];
    __shared__ float s_col[TS];
    __shared__ int   labA[TS];
    __shared__ int   labB[TS];

    int tid = threadIdx.x;

    // load tiles (row fast across lanes -> conflict-free smem stores)
    #pragma unroll
    for (int it = 0; it < 16; it++) {
        int idx = tid + it * 256;              // 0..4095
        int row = idx & 127;
        int c4  = idx >> 7;                    // 0..31
        float4 va = *(const float4*)&g_U[(size_t)(I0 + row) * DIM + c4 * 4];
        float4 vb = *(const float4*)&g_U[(size_t)(J0 + row) * DIM + c4 * 4];
        *(float4*)&A_s[row * LDSTR + c4 * 4] = va;
        *(float4*)&B_s[row * LDSTR + c4 * 4] = vb;
    }
    if (tid < TS) {
        labA[tid] = g_lab[(I0 + tid) & (BSZ - 1)];
        labB[tid] = g_lab[(J0 + tid) & (BSZ - 1)];
        s_row[tid] = 0.0f;
        s_col[tid] = 0.0f;
    }
    __syncthreads();

    int tn = tid & 15, tm = tid >> 4;          // 16x16 thread grid, 8x8 micro-tile
    const float* ap = &A_s[(tm * 8) * LDSTR];
    const float* bp = &B_s[(tn * 8) * LDSTR];

    float acc[8][8];
    #pragma unroll
    for (int r = 0; r < 8; r++)
        #pragma unroll
        for (int c = 0; c < 8; c++) acc[r][c] = 0.0f;

    #pragma unroll 1
    for (int k = 0; k < DIM; k += 4) {
        float4 a[8], b[8];
        #pragma unroll
        for (int r = 0; r < 8; r++) a[r] = *(const float4*)&ap[r * LDSTR + k];
        #pragma unroll
        for (int c = 0; c < 8; c++) b[c] = *(const float4*)&bp[c * LDSTR + k];
        #pragma unroll
        for (int r = 0; r < 8; r++)
            #pragma unroll
            for (int c = 0; c < 8; c++) {
                acc[r][c] += a[r].x * b[c].x;
                acc[r][c] += a[r].y * b[c].y;
                acc[r][c] += a[r].z * b[c].z;
                acc[r][c] += a[r].w * b[c].w;
            }
    }

    // epilogue: exp + neg mask, per-thread partial row/col sums
    int myl[8];
    #pragma unroll
    for (int r = 0; r < 8; r++) myl[r] = labA[tm * 8 + r];
    int coll[8];
    #pragma unroll
    for (int c = 0; c < 8; c++) coll[c] = labB[tn * 8 + c];

    float rs[8], cs[8];
    #pragma unroll
    for (int r = 0; r < 8; r++) rs[r] = 0.0f;
    #pragma unroll
    for (int c = 0; c < 8; c++) cs[c] = 0.0f;

    #pragma unroll
    for (int r = 0; r < 8; r++)
        #pragma unroll
        for (int c = 0; c < 8; c++) {
            float l = acc[r][c] * INV_T;
            float e = (myl[r] != coll[c]) ? __expf(l) : 0.0f;
            rs[r] += e;
            cs[c] += e;
        }

    #pragma unroll
    for (int r = 0; r < 8; r++) atomicAdd(&s_row[tm * 8 + r], rs[r]);
    if (!diag) {
        #pragma unroll
        for (int c = 0; c < 8; c++) atomicAdd(&s_col[tn * 8 + c], cs[c]);
    }
    __syncthreads();

    if (tid < TS) {
        atomicAdd(&g_S[I0 + tid], s_row[tid]);
        if (!diag) atomicAdd(&g_S[J0 + tid], s_col[tid]);
    }
}

// ---------------------------------------------------------------------------
// Kernel C: positive pairs only. One warp per anchor row i: scan labels,
//           recompute the ~82 positive dots, accumulate log-prob sum.
// ---------------------------------------------------------------------------
__global__ void loss_kernel() {
    int t    = blockIdx.x * blockDim.x + threadIdx.x;
    int i    = t >> 5;
    int lane = t & 31;
    if (i >= NROWS) return;

    int lab_i = g_lab[i & (BSZ - 1)];
    float4 mu = ((const float4*)&g_U[(size_t)i * DIM])[lane];

    float sum = 0.0f;
    for (int b0 = 0; b0 < BSZ; b0 += 32) {
        int lb = g_lab[b0 + lane];
        unsigned m = __ballot_sync(0xffffffffu, lb == lab_i);
        while (m) {
            int p = __ffs(m) - 1;
            m &= m - 1;
            int bp = b0 + p;
            #pragma unroll
            for (int v = 0; v < 2; v++) {
                int j = (v << 12) + bp;
                if (j == i) continue;
                float4 uj = ((const float4*)&g_U[(size_t)j * DIM])[lane];
                float d = mu.x * uj.x + mu.y * uj.y + mu.z * uj.z + mu.w * uj.w;
                #pragma unroll
                for (int o = 16; o > 0; o >>= 1)
                    d += __shfl_xor_sync(0xffffffffu, d, o);
                float l = d * INV_T;
                sum += l - __logf(g_S[j] + __expf(l));
            }
        }
    }
    if (lane == 0) atomicAdd(&g_loss, (double)sum);
}

// ---------------------------------------------------------------------------
// Kernel D: final scalar
// ---------------------------------------------------------------------------
__global__ void finish_kernel(float* out) {
    out[0] = (float)(-g_loss / (double)NROWS);   // T/BASE_T == 1
}

extern "C" void kernel_launch(void* const* d_in, const int* in_sizes, int n_in,
                              void* d_out, int out_size) {
    const float* feat   = (const float*)d_in[0];
    const void*  labels = d_in[1];
    float*       out    = (float*)d_out;

    prep_kernel<<<1024, 256>>>(feat, labels);

    size_t smemB = (size_t)2 * TS * LDSTR * sizeof(float);   // 135168 B
    cudaFuncSetAttribute(gemm_negsum_kernel,
                         cudaFuncAttributeMaxDynamicSharedMemorySize, (int)smemB);
    gemm_negsum_kernel<<<dim3(64, 64), 256, smemB>>>();

    loss_kernel<<<1024, 256>>>();
    finish_kernel<<<1, 1>>>(out);
}

// round 4
// speedup vs baseline: 3.9779x; 3.9779x over previous
#include <cuda_runtime.h>
#include <cuda_bf16.h>
#include <cstdint>
#include <math.h>

#define BSZ   4096
#define NROWS 8192
#define DIM   128
#define TS    128
#define INV_T (1.0f / 0.07f)

// ---------------- scratch (__device__ globals; no allocs allowed) ----------
__device__ float          g_U  [NROWS * DIM];
__device__ __nv_bfloat16  g_Uhi[NROWS * DIM];
__device__ __nv_bfloat16  g_Ulo[NROWS * DIM];
__device__ float          g_S  [NROWS];
__device__ int            g_lab[BSZ];
__device__ double         g_loss;

// ---------------- warp-level MMA helpers (base sm_103-safe PTX) ------------
__device__ __forceinline__ uint32_t smem_u32(const void* p) {
    uint32_t a;
    asm("{ .reg .u64 t; cvta.to.shared.u64 t, %1; cvt.u32.u64 %0, t; }"
        : "=r"(a) : "l"(p));
    return a;
}

__device__ __forceinline__ void ldmatrix_x4(uint32_t* r, uint32_t addr) {
    asm volatile("ldmatrix.sync.aligned.m8n8.x4.shared.b16 {%0,%1,%2,%3}, [%4];"
                 : "=r"(r[0]), "=r"(r[1]), "=r"(r[2]), "=r"(r[3]) : "r"(addr));
}

__device__ __forceinline__ void mma_16816_bf16(float* d, const uint32_t* a,
                                               const uint32_t* b) {
    asm volatile(
        "mma.sync.aligned.m16n8k16.row.col.f32.bf16.bf16.f32 "
        "{%0,%1,%2,%3}, {%4,%5,%6,%7}, {%8,%9}, {%0,%1,%2,%3};"
        : "+f"(d[0]), "+f"(d[1]), "+f"(d[2]), "+f"(d[3])
        : "r"(a[0]), "r"(a[1]), "r"(a[2]), "r"(a[3]), "r"(b[0]), "r"(b[1]));
}

// ---------------------------------------------------------------------------
// Kernel A: normalize rows of cf; produce fp32 + bf16 hi/lo copies; zero accs
// ---------------------------------------------------------------------------
__global__ void prep_kernel(const float* __restrict__ feat,
                            const void* __restrict__ labels_raw) {
    int t    = blockIdx.x * blockDim.x + threadIdx.x;
    int warp = t >> 5;
    int lane = t & 31;

    if (t < NROWS) g_S[t] = 0.0f;
    if (t == 0)    g_loss = 0.0;
    if (t < BSZ) {
        const int* li = (const int*)labels_raw;
        bool is64 = true;
        #pragma unroll
        for (int q = 1; q < 64; q += 2) is64 &= (li[q] == 0);
        g_lab[t] = is64 ? (int)((const long long*)labels_raw)[t] : li[t];
    }

    if (warp >= NROWS) return;
    int i = warp;
    int v = i >> 12;
    int b = i & (BSZ - 1);
    const float4* src = (const float4*)&feat[(size_t)(b * 2 + v) * DIM];
    float4 f = src[lane];
    float ss = f.x * f.x + f.y * f.y + f.z * f.z + f.w * f.w;
    #pragma unroll
    for (int o = 16; o > 0; o >>= 1) ss += __shfl_xor_sync(0xffffffffu, ss, o);
    float rn = rsqrtf(ss);
    float u[4] = { f.x * rn, f.y * rn, f.z * rn, f.w * rn };
    ((float4*)&g_U[(size_t)i * DIM])[lane] = make_float4(u[0], u[1], u[2], u[3]);

    __nv_bfloat16 hi[4], lo[4];
    #pragma unroll
    for (int q = 0; q < 4; q++) {
        hi[q] = __float2bfloat16(u[q]);
        lo[q] = __float2bfloat16(u[q] - __bfloat162float(hi[q]));
    }
    ((uint2*)&g_Uhi[(size_t)i * DIM])[lane] =
        make_uint2(((uint32_t*)hi)[0], ((uint32_t*)hi)[1]);
    ((uint2*)&g_Ulo[(size_t)i * DIM])[lane] =
        make_uint2(((uint32_t*)lo)[0], ((uint32_t*)lo)[1]);
}

// ---------------------------------------------------------------------------
// Kernel B: mma.sync bf16-split GEMM over upper-triangle 128x128 tiles.
// logits = (Ahi*Bhi^T + Ahi*Blo^T + Alo*Bhi^T)/T, fp32 accum in registers.
// Fused exp + neg-mask; row sums AND (symmetry) column sums -> g_S.
// ---------------------------------------------------------------------------
// SMEM tile layout: [128 rows][128 bf16] = row*256B; 16B chunk c stored at
// (c ^ (row&7)) so both stores and ldmatrix row-gathers are conflict-free.
#define TILE_B   32768
#define SM_AHI   0
#define SM_ALO   (SM_AHI + TILE_B)
#define SM_BHI   (SM_ALO + TILE_B)
#define SM_BLO   (SM_BHI + TILE_B)
#define SM_TOTAL (4 * TILE_B)          // 131072 B dynamic

extern __shared__ char smemB[];

__device__ __forceinline__ uint32_t sw_off(int row, int k_elem) {
    // element address within tile (k_elem must index bf16 elements)
    int chunk = k_elem >> 3;
    int within = k_elem & 7;
    return (uint32_t)(row * 256 + ((chunk ^ (row & 7)) << 4) + within * 2);
}

__device__ __forceinline__ void load_tile(const __nv_bfloat16* __restrict__ src,
                                          char* dst, int tid) {
    #pragma unroll
    for (int it = 0; it < 8; it++) {
        int idx = tid + it * 256;        // 2048 chunks of 16B
        int row = idx >> 4;
        int c   = idx & 15;
        uint4 v = *(const uint4*)(src + (size_t)row * DIM + c * 8);
        *(uint4*)(dst + row * 256 + ((c ^ (row & 7)) << 4)) = v;
    }
}

__global__ __launch_bounds__(256, 1) void gemm_negsum_kernel() {
    int bi = blockIdx.y, bj = blockIdx.x;
    if (bj < bi) return;
    bool diag = (bi == bj);
    int I0 = bi * TS, J0 = bj * TS;

    __shared__ int   labA[TS], labB[TS];
    __shared__ float s_row[TS], s_col[TS];

    int tid  = threadIdx.x;
    int wid  = tid >> 5;
    int lane = tid & 31;

    load_tile(&g_Uhi[(size_t)I0 * DIM], smemB + SM_AHI, tid);
    load_tile(&g_Ulo[(size_t)I0 * DIM], smemB + SM_ALO, tid);
    load_tile(&g_Uhi[(size_t)J0 * DIM], smemB + SM_BHI, tid);
    load_tile(&g_Ulo[(size_t)J0 * DIM], smemB + SM_BLO, tid);
    if (tid < TS) {
        labA[tid] = g_lab[(I0 + tid) & (BSZ - 1)];
        labB[tid] = g_lab[(J0 + tid) & (BSZ - 1)];
        s_row[tid] = 0.0f;
        s_col[tid] = 0.0f;
    }
    __syncthreads();

    // warp grid: 4 (m) x 2 (n); warp tile 32 (m) x 64 (n)
    int wm = wid & 3, wn = wid >> 2;
    int m_base = wm * 32, n_base = wn * 64;

    float acc[2][8][4];
    #pragma unroll
    for (int mt = 0; mt < 2; mt++)
        #pragma unroll
        for (int nt = 0; nt < 8; nt++)
            #pragma unroll
            for (int q = 0; q < 4; q++) acc[mt][nt][q] = 0.0f;

    uint32_t a_base[3], b_base[3];
    a_base[0] = smem_u32(smemB + SM_AHI);
    a_base[1] = smem_u32(smemB + SM_AHI);
    a_base[2] = smem_u32(smemB + SM_ALO);
    b_base[0] = smem_u32(smemB + SM_BHI);
    b_base[1] = smem_u32(smemB + SM_BLO);
    b_base[2] = smem_u32(smemB + SM_BHI);

    #pragma unroll 1
    for (int p = 0; p < 3; p++) {
        uint32_t ab = a_base[p], bb = b_base[p];
        #pragma unroll
        for (int ks = 0; ks < 8; ks++) {
            int k0 = ks * 16;
            // A fragments: 2 x ldmatrix.x4 (m16k16 each)
            uint32_t af[2][4];
            #pragma unroll
            for (int mt = 0; mt < 2; mt++) {
                int row = m_base + mt * 16 + (lane & 15);
                int k   = k0 + ((lane >> 4) << 3);
                ldmatrix_x4(af[mt], ab + sw_off(row, k));
            }
            // B fragments: 4 x ldmatrix.x4, each covers two n8 blocks
            uint32_t bf[8][2];
            #pragma unroll
            for (int np = 0; np < 4; np++) {
                uint32_t r4[4];
                int n = n_base + np * 16 + (lane & 7) + ((lane >> 4) << 3);
                int k = k0 + (((lane >> 3) & 1) << 3);
                ldmatrix_x4(r4, bb + sw_off(n, k));
                bf[np * 2 + 0][0] = r4[0]; bf[np * 2 + 0][1] = r4[1];
                bf[np * 2 + 1][0] = r4[2]; bf[np * 2 + 1][1] = r4[3];
            }
            #pragma unroll
            for (int mt = 0; mt < 2; mt++)
                #pragma unroll
                for (int nt = 0; nt < 8; nt++)
                    mma_16816_bf16(acc[mt][nt], af[mt], bf[nt]);
        }
    }

    // ---------------- epilogue: exp + neg mask, row & col sums -------------
    int gid = lane >> 2;         // 0..7  (row within 8-block)
    int qid = lane & 3;          // col pair selector

    int la[2][2], lb[8][2];
    #pragma unroll
    for (int mt = 0; mt < 2; mt++)
        #pragma unroll
        for (int h = 0; h < 2; h++)
            la[mt][h] = labA[m_base + mt * 16 + h * 8 + gid];
    #pragma unroll
    for (int nt = 0; nt < 8; nt++)
        #pragma unroll
        for (int qq = 0; qq < 2; qq++)
            lb[nt][qq] = labB[n_base + nt * 8 + qid * 2 + qq];

    float rs[2][2] = {{0, 0}, {0, 0}};
    float cs[8][2];
    #pragma unroll
    for (int nt = 0; nt < 8; nt++) cs[nt][0] = cs[nt][1] = 0.0f;

    #pragma unroll
    for (int mt = 0; mt < 2; mt++)
        #pragma unroll
        for (int nt = 0; nt < 8; nt++)
            #pragma unroll
            for (int h = 0; h < 2; h++)
                #pragma unroll
                for (int qq = 0; qq < 2; qq++) {
                    float l = acc[mt][nt][h * 2 + qq] * INV_T;
                    float e = (la[mt][h] != lb[nt][qq]) ? __expf(l) : 0.0f;
                    rs[mt][h] += e;
                    cs[nt][qq] += e;
                }

    // row sums: reduce across lanes sharing gid (xor 1,2); qid==0 writes
    #pragma unroll
    for (int mt = 0; mt < 2; mt++)
        #pragma unroll
        for (int h = 0; h < 2; h++) {
            float v = rs[mt][h];
            v += __shfl_xor_sync(0xffffffffu, v, 1);
            v += __shfl_xor_sync(0xffffffffu, v, 2);
            if (qid == 0)
                atomicAdd(&s_row[m_base + mt * 16 + h * 8 + gid], v);
        }
    // col sums: reduce across lanes sharing qid (xor 4,8,16); gid==0 writes
    if (!diag) {
        #pragma unroll
        for (int nt = 0; nt < 8; nt++)
            #pragma unroll
            for (int qq = 0; qq < 2; qq++) {
                float v = cs[nt][qq];
                v += __shfl_xor_sync(0xffffffffu, v, 4);
                v += __shfl_xor_sync(0xffffffffu, v, 8);
                v += __shfl_xor_sync(0xffffffffu, v, 16);
                if (gid == 0)
                    atomicAdd(&s_col[n_base + nt * 8 + qid * 2 + qq], v);
            }
    }
    __syncthreads();

    if (tid < TS) {
        atomicAdd(&g_S[I0 + tid], s_row[tid]);
        if (!diag) atomicAdd(&g_S[J0 + tid], s_col[tid]);
    }
}

// ---------------------------------------------------------------------------
// Kernel C: positive pairs only (one warp per anchor row)
// ---------------------------------------------------------------------------
__global__ void loss_kernel() {
    int t    = blockIdx.x * blockDim.x + threadIdx.x;
    int i    = t >> 5;
    int lane = t & 31;
    if (i >= NROWS) return;

    int lab_i = g_lab[i & (BSZ - 1)];
    float4 mu = ((const float4*)&g_U[(size_t)i * DIM])[lane];

    float sum = 0.0f;
    for (int b0 = 0; b0 < BSZ; b0 += 32) {
        int lb = g_lab[b0 + lane];
        unsigned msk = __ballot_sync(0xffffffffu, lb == lab_i);
        while (msk) {
            int p = __ffs(msk) - 1;
            msk &= msk - 1;
            int bp = b0 + p;
            #pragma unroll
            for (int v = 0; v < 2; v++) {
                int j = (v << 12) + bp;
                if (j == i) continue;
                float4 uj = ((const float4*)&g_U[(size_t)j * DIM])[lane];
                float d = mu.x * uj.x + mu.y * uj.y + mu.z * uj.z + mu.w * uj.w;
                #pragma unroll
                for (int o = 16; o > 0; o >>= 1)
                    d += __shfl_xor_sync(0xffffffffu, d, o);
                float l = d * INV_T;
                sum += l - __logf(g_S[j] + __expf(l));
            }
        }
    }
    if (lane == 0) atomicAdd(&g_loss, (double)sum);
}

__global__ void finish_kernel(float* out) {
    out[0] = (float)(-g_loss / (double)NROWS);
}

extern "C" void kernel_launch(void* const* d_in, const int* in_sizes, int n_in,
                              void* d_out, int out_size) {
    const float* feat   = (const float*)d_in[0];
    const void*  labels = d_in[1];
    float*       out    = (float*)d_out;

    prep_kernel<<<1024, 256>>>(feat, labels);

    cudaFuncSetAttribute(gemm_negsum_kernel,
                         cudaFuncAttributeMaxDynamicSharedMemorySize, SM_TOTAL);
    gemm_negsum_kernel<<<dim3(64, 64), 256, SM_TOTAL>>>();

    loss_kernel<<<1024, 256>>>();
    finish_kernel<<<1, 1>>>(out);
}